// round 2
// baseline (speedup 1.0000x reference)
#include <cuda_runtime.h>
#include <math.h>

// GAT layer, algebraically folded:
//   Wt = attn1_w[:, :64] @ align_w   (16x64)
//   Wn = attn1_w[:, 64:] @ align_w   (16x64)
//   cb = (attn1_w[:, :64] + attn1_w[:, 64:]) @ align_b + attn1_b
//   pre[n][h] = Wt@x_t + Wn@x_n + cb ; e = leaky(attn2 @ relu(pre) + b2)
//   a = softmax(e); s = sum_n a_n x_n ; out = elu(align_w @ s + align_b)

#define BTOT   65536
#define NGRP   (BTOT / 4)
#define NN     35
#define PITCH  66      // smem row pitch (floats), rows are c-interleaved pairs
#define NROWS  36      // 35 neighbors + x_target as row 35
#define GRID   2048

__device__ float WnP_g[64 * 16];
__device__ float WtP_g[64 * 16];
__device__ float CB_g[16];

// ---------------- prologue: fold weights ----------------
__global__ void prep_kernel(const float* __restrict__ align_w,
                            const float* __restrict__ align_b,
                            const float* __restrict__ a1w,
                            const float* __restrict__ a1b) {
    int tid = threadIdx.x;
    for (int idx = tid; idx < 1024; idx += blockDim.x) {
        int c = idx >> 4, h = idx & 15;
        float st = 0.f, sn = 0.f;
        for (int d = 0; d < 64; d++) {
            float aw = align_w[d * 64 + c];
            st = fmaf(a1w[h * 128 + d], aw, st);
            sn = fmaf(a1w[h * 128 + 64 + d], aw, sn);
        }
        int pos = 2 * (c & 31) + (c >> 5);   // interleaved (c, c+32) pair layout
        WtP_g[pos * 16 + h] = st;
        WnP_g[pos * 16 + h] = sn;
    }
    if (tid < 16) {
        float s = 0.f;
        for (int d = 0; d < 64; d++)
            s += (a1w[tid * 128 + d] + a1w[tid * 128 + 64 + d]) * align_b[d];
        CB_g[tid] = s + a1b[tid];
    }
}

// ---------------- main fused kernel ----------------
__global__ __launch_bounds__(128, 4)
void gat_kernel(const float* __restrict__ xt,
                const float* __restrict__ xn,
                const float* __restrict__ align_w,
                const float* __restrict__ align_b,
                const float* __restrict__ a2w,
                const float* __restrict__ a2b,
                float* __restrict__ out) {
    __shared__ __align__(16) float xs[4][NROWS * PITCH];
    __shared__ __align__(16) float Wn_s[1024];
    __shared__ __align__(16) float Wt_s[1024];
    __shared__ __align__(16) float cb_s[16];
    __shared__ __align__(16) float a_s[4][40];
    __shared__ __align__(16) float s_s[4][64];
    __shared__ __align__(16) float part[4][64];

    const int tid  = threadIdx.x;
    const int wid  = tid >> 5;
    const int lane = tid & 31;
    const int nI   = lane & 7;       // neighbor index within warp grid
    const int hI   = lane >> 3;      // h-group (4 h's each)
    const int h0   = hI * 4;

    // load folded weights into smem once per block
    for (int i = tid; i < 1024; i += 128) { Wn_s[i] = WnP_g[i]; Wt_s[i] = WtP_g[i]; }
    if (tid < 16) cb_s[tid] = CB_g[tid];

    // register-cache a half-row of align_w per thread (for final matvec)
    const int d = tid & 63, half = tid >> 6;
    float ar[32];
#pragma unroll
    for (int i = 0; i < 32; i++) ar[i] = align_w[d * 64 + half * 32 + i];
    const float ab = align_b[d];

    float a2r[4];
#pragma unroll
    for (int k = 0; k < 4; k++) a2r[k] = a2w[h0 + k];
    const float a2bias = a2b[0];

    __syncthreads();

    for (int g = blockIdx.x; g < NGRP; g += GRID) {
        const int b = g * 4 + wid;
        float* xw = xs[wid];

        // ---- phase 1: stage x_neigh[b] (+ x_target as row 35), (c,c+32) interleaved
        {
            const float* src = xn + (size_t)b * (NN * 64);
#pragma unroll 5
            for (int n = 0; n < NN; n++) {
                float v0 = src[n * 64 + lane];
                float v1 = src[n * 64 + 32 + lane];
                *(float2*)&xw[n * PITCH + 2 * lane] = make_float2(v0, v1);
            }
            float t0 = xt[(size_t)b * 64 + lane];
            float t1 = xt[(size_t)b * 64 + 32 + lane];
            *(float2*)&xw[35 * PITCH + 2 * lane] = make_float2(t0, t1);
        }
        __syncwarp();

        // ---- phase 2: u[n][h] = Wn @ x_n  (register-tiled warp GEMM 40x16 <- 64)
        float u[5][4];
#pragma unroll
        for (int j = 0; j < 5; j++)
#pragma unroll
            for (int k = 0; k < 4; k++) u[j][k] = 0.f;

        const int  row4 = (nI < 3) ? (nI + 32) : 35;   // safe in-bounds read
        const bool v4   = (nI < 3);

#pragma unroll 4
        for (int p = 0; p < 32; p++) {
            float4 wA = *(const float4*)&Wn_s[(2 * p) * 16 + h0];
            float4 wB = *(const float4*)&Wn_s[(2 * p + 1) * 16 + h0];
#pragma unroll
            for (int j = 0; j < 4; j++) {
                float2 xv = *(const float2*)&xw[(nI + 8 * j) * PITCH + 2 * p];
                u[j][0] = fmaf(xv.x, wA.x, u[j][0]); u[j][0] = fmaf(xv.y, wB.x, u[j][0]);
                u[j][1] = fmaf(xv.x, wA.y, u[j][1]); u[j][1] = fmaf(xv.y, wB.y, u[j][1]);
                u[j][2] = fmaf(xv.x, wA.z, u[j][2]); u[j][2] = fmaf(xv.y, wB.z, u[j][2]);
                u[j][3] = fmaf(xv.x, wA.w, u[j][3]); u[j][3] = fmaf(xv.y, wB.w, u[j][3]);
            }
            {
                float2 xv = *(const float2*)&xw[row4 * PITCH + 2 * p];
                if (!v4) { xv.x = 0.f; xv.y = 0.f; }
                u[4][0] = fmaf(xv.x, wA.x, u[4][0]); u[4][0] = fmaf(xv.y, wB.x, u[4][0]);
                u[4][1] = fmaf(xv.x, wA.y, u[4][1]); u[4][1] = fmaf(xv.y, wB.y, u[4][1]);
                u[4][2] = fmaf(xv.x, wA.z, u[4][2]); u[4][2] = fmaf(xv.y, wB.z, u[4][2]);
                u[4][3] = fmaf(xv.x, wA.w, u[4][3]); u[4][3] = fmaf(xv.y, wB.w, u[4][3]);
            }
        }

        // ---- target path: ub[h] = Wt @ x_t + cb, split over nI then reduced
        float ub[4] = {0.f, 0.f, 0.f, 0.f};
#pragma unroll
        for (int q = 0; q < 4; q++) {
            int p = nI * 4 + q;
            float2 xv = *(const float2*)&xw[35 * PITCH + 2 * p];
            float4 wA = *(const float4*)&Wt_s[(2 * p) * 16 + h0];
            float4 wB = *(const float4*)&Wt_s[(2 * p + 1) * 16 + h0];
            ub[0] = fmaf(xv.x, wA.x, ub[0]); ub[0] = fmaf(xv.y, wB.x, ub[0]);
            ub[1] = fmaf(xv.x, wA.y, ub[1]); ub[1] = fmaf(xv.y, wB.y, ub[1]);
            ub[2] = fmaf(xv.x, wA.z, ub[2]); ub[2] = fmaf(xv.y, wB.z, ub[2]);
            ub[3] = fmaf(xv.x, wA.w, ub[3]); ub[3] = fmaf(xv.y, wB.w, ub[3]);
        }
#pragma unroll
        for (int m = 1; m <= 4; m <<= 1) {
#pragma unroll
            for (int k = 0; k < 4; k++) ub[k] += __shfl_xor_sync(0xffffffffu, ub[k], m);
        }
        {
            float4 cbv = *(const float4*)&cb_s[h0];
            ub[0] += cbv.x; ub[1] += cbv.y; ub[2] += cbv.z; ub[3] += cbv.w;
        }

        // ---- phase 3: e_n, leaky relu, softmax over n
        float e[5];
#pragma unroll
        for (int j = 0; j < 5; j++) {
            float pe = 0.f;
#pragma unroll
            for (int k = 0; k < 4; k++) {
                float hv = fmaxf(u[j][k] + ub[k], 0.f);
                pe = fmaf(a2r[k], hv, pe);
            }
            pe += __shfl_xor_sync(0xffffffffu, pe, 8);
            pe += __shfl_xor_sync(0xffffffffu, pe, 16);
            float ev = pe + a2bias;
            e[j] = ev > 0.f ? ev : 0.2f * ev;
        }
        if (nI >= 3) e[4] = -INFINITY;   // n >= 35 invalid

        float mx = e[0];
#pragma unroll
        for (int j = 1; j < 5; j++) mx = fmaxf(mx, e[j]);
#pragma unroll
        for (int m = 1; m <= 4; m <<= 1) mx = fmaxf(mx, __shfl_xor_sync(0xffffffffu, mx, m));

        float ax[5]; float sum = 0.f;
#pragma unroll
        for (int j = 0; j < 5; j++) { ax[j] = __expf(e[j] - mx); sum += ax[j]; }
#pragma unroll
        for (int m = 1; m <= 4; m <<= 1) sum += __shfl_xor_sync(0xffffffffu, sum, m);
        float rinv = 1.0f / sum;

        if (hI == 0) {
#pragma unroll
            for (int j = 0; j < 5; j++) {
                int n = nI + 8 * j;
                if (n < 35) a_s[wid][n] = ax[j] * rinv;
            }
            if (nI < 5) a_s[wid][35 + nI] = 0.f;   // pad rows (incl. x_t row) -> 0
        }
        __syncwarp();

        // ---- phase 4: s[c] = sum_n a_n x_n[c]
        float slo = 0.f, shi = 0.f;
#pragma unroll 2
        for (int q = 0; q < 18; q++) {
            float2 av = *(const float2*)&a_s[wid][2 * q];
            float2 x0 = *(const float2*)&xw[(2 * q) * PITCH + 2 * lane];
            float2 x1 = *(const float2*)&xw[(2 * q + 1) * PITCH + 2 * lane];
            slo = fmaf(av.x, x0.x, slo); slo = fmaf(av.y, x1.x, slo);
            shi = fmaf(av.x, x0.y, shi); shi = fmaf(av.y, x1.y, shi);
        }
        s_s[wid][lane]      = slo;
        s_s[wid][lane + 32] = shi;
        __syncthreads();

        // ---- phase 5: out = elu(align_w @ s + align_b), block-cooperative,
        //      align_w register-cached (ar), half-split over c
        float acc[4];
#pragma unroll
        for (int bb = 0; bb < 4; bb++) {
            float a = 0.f;
            const float4* sp = (const float4*)&s_s[bb][half * 32];
#pragma unroll
            for (int i4 = 0; i4 < 8; i4++) {
                float4 sv = sp[i4];
                a = fmaf(ar[i4 * 4 + 0], sv.x, a);
                a = fmaf(ar[i4 * 4 + 1], sv.y, a);
                a = fmaf(ar[i4 * 4 + 2], sv.z, a);
                a = fmaf(ar[i4 * 4 + 3], sv.w, a);
            }
            acc[bb] = a;
        }
        if (half == 1) {
#pragma unroll
            for (int bb = 0; bb < 4; bb++) part[bb][d] = acc[bb];
        }
        __syncthreads();
        if (half == 0) {
#pragma unroll
            for (int bb = 0; bb < 4; bb++) {
                float o = acc[bb] + part[bb][d] + ab;
                o = (o > 0.f) ? o : expm1f(o);
                out[(size_t)(g * 4 + bb) * 64 + d] = o;
            }
        }
    }
}

extern "C" void kernel_launch(void* const* d_in, const int* in_sizes, int n_in,
                              void* d_out, int out_size) {
    const float* x_target = (const float*)d_in[0];
    const float* x_neigh  = (const float*)d_in[1];
    const float* align_w  = (const float*)d_in[2];
    const float* align_b  = (const float*)d_in[3];
    const float* attn1_w  = (const float*)d_in[4];
    const float* attn1_b  = (const float*)d_in[5];
    const float* attn2_w  = (const float*)d_in[6];
    const float* attn2_b  = (const float*)d_in[7];
    float* out = (float*)d_out;

    prep_kernel<<<1, 256>>>(align_w, align_b, attn1_w, attn1_b);
    gat_kernel<<<GRID, 128>>>(x_target, x_neigh, align_w, align_b,
                              attn2_w, attn2_b, out);
}

// round 3
// speedup vs baseline: 1.4846x; 1.4846x over previous
#include <cuda_runtime.h>
#include <math.h>

// GAT layer, algebraically folded:
//   Wn = attn1_w[:,64:] @ align_w  (16x64), Wt = attn1_w[:,:64] @ align_w
//   cb = (attn1_w[:,:64]+attn1_w[:,64:]) @ align_b + attn1_b
//   e_n = leaky(attn2 @ relu(Wn x_n + Wt x_t + cb) + b2); a = softmax(e)
//   out = elu(align_w @ (sum_n a_n x_n) + align_b)

#define BTOT 65536
#define NGRP (BTOT / 4)
#define NN   35
#define GRID 1480

typedef unsigned long long ull;

__device__ float4 WnP_g[256];  // folded Wn, natural [c][h] (float view c*16+h)
__device__ float4 WtP_g[256];  // folded Wt, natural [c][h]
__device__ float4 CB_g[4];

__device__ __forceinline__ ull splat2(float a) {
    ull r; asm("mov.b64 %0, {%1, %1};" : "=l"(r) : "f"(a)); return r;
}
__device__ __forceinline__ void fma2(ull& acc, ull a, ull b) {
    asm("fma.rn.f32x2 %0, %1, %2, %0;" : "+l"(acc) : "l"(a), "l"(b));
}
__device__ __forceinline__ float2 unpack2(ull v) {
    float2 r; asm("mov.b64 {%0, %1}, %2;" : "=f"(r.x), "=f"(r.y) : "l"(v)); return r;
}

// ---------------- prologue: fold weights ----------------
__global__ void prep_kernel(const float* __restrict__ align_w,
                            const float* __restrict__ align_b,
                            const float* __restrict__ a1w,
                            const float* __restrict__ a1b) {
    int idx = blockIdx.x * blockDim.x + threadIdx.x;
    if (idx < 1024) {
        int c = idx >> 4, h = idx & 15;
        float st = 0.f, sn = 0.f;
        for (int d = 0; d < 64; d++) {
            float aw = align_w[d * 64 + c];
            st = fmaf(a1w[h * 128 + d],      aw, st);
            sn = fmaf(a1w[h * 128 + 64 + d], aw, sn);
        }
        ((float*)WtP_g)[c * 16 + h] = st;
        ((float*)WnP_g)[c * 16 + h] = sn;
    } else if (idx < 1040) {
        int h = idx - 1024;
        float s = 0.f;
        for (int d = 0; d < 64; d++)
            s += (a1w[h * 128 + d] + a1w[h * 128 + 64 + d]) * align_b[d];
        ((float*)CB_g)[h] = s + a1b[h];
    }
}

// ---------------- main fused kernel ----------------
__global__ __launch_bounds__(128, 5)
void gat_kernel(const float* __restrict__ xt,
                const float* __restrict__ xn,
                const float* __restrict__ align_w,
                const float* __restrict__ align_b,
                const float* __restrict__ a2w,
                const float* __restrict__ a2b,
                float* __restrict__ out) {
    // x tile: 36 rows x 16 float4 chunks, chunk index XOR-swizzled by (row&7)
    __shared__ __align__(16) float4 xs4[4][576];       // 36864 B
    __shared__ __align__(16) float  Wn_s[1024];        //  4096 B
    __shared__ __align__(8)  float  a_s[4][36];        //   576 B
    __shared__ __align__(16) float  s_s[4][64];        //  1024 B
    __shared__ __align__(16) float  part[4][64];       //  1024 B

    const int tid  = threadIdx.x;
    const int wid  = tid >> 5;
    const int lane = tid & 31;
    const int nI   = lane & 7;
    const int hI   = lane >> 3;

    for (int i = tid; i < 1024; i += 128) Wn_s[i] = ((const float*)WnP_g)[i];

    // phase-5 register cache: align_w half-row per thread (iteration-invariant)
    const int d = tid & 63, half = tid >> 6;
    float ar[32];
#pragma unroll
    for (int i = 0; i < 32; i++) ar[i] = align_w[d * 64 + half * 32 + i];
    const float ab = align_b[d];

    float a2r[4];
#pragma unroll
    for (int k = 0; k < 4; k++) a2r[k] = a2w[hI * 4 + k];
    const float a2bias = a2b[0];

    __syncthreads();

    for (int g = blockIdx.x; g < NGRP; g += GRID) {
        const int b = g * 4 + wid;
        float4* xw4 = xs4[wid];
        const float* xw = (const float*)xw4;

        // ---- phase 1: stage x_neigh (35 rows) + x_target (row 35), float4 + swizzle
        {
            const float4* src4 = (const float4*)xn + (size_t)b * 560;
            const float4* xt4  = (const float4*)xt + (size_t)b * 16;
#pragma unroll
            for (int k = 0; k < 18; k++) {
                int idx = k * 32 + lane;
                float4 v = (idx < 560) ? src4[idx] : xt4[idx - 560];
                int row = idx >> 4, cq = idx & 15;
                xw4[row * 16 + (cq ^ (row & 7))] = v;
            }
        }
        __syncwarp();

        // ---- phase 2: u[n][h] = Wn @ x_n  (f32x2-packed warp GEMM 40x16 <- 64)
        ull u2[5][2];
#pragma unroll
        for (int j = 0; j < 5; j++) { u2[j][0] = 0ull; u2[j][1] = 0ull; }

        const int  row4 = (nI < 3) ? (nI + 32) : 35;
        const bool v4   = (nI < 3);

#pragma unroll 4
        for (int p4 = 0; p4 < 16; p4++) {
            const float* wb = &Wn_s[p4 * 64 + hI * 4];
            ull w0l = *(const ull*)&wb[0],  w0h = *(const ull*)&wb[2];
            ull w1l = *(const ull*)&wb[16], w1h = *(const ull*)&wb[18];
            ull w2l = *(const ull*)&wb[32], w2h = *(const ull*)&wb[34];
            ull w3l = *(const ull*)&wb[48], w3h = *(const ull*)&wb[50];
#pragma unroll
            for (int j = 0; j < 5; j++) {
                int row = (j < 4) ? (nI + 8 * j) : row4;
                float4 xv = xw4[row * 16 + (p4 ^ (row & 7))];
                if (j == 4 && !v4) { xv.x = 0.f; xv.y = 0.f; xv.z = 0.f; xv.w = 0.f; }
                ull a0 = splat2(xv.x), a1 = splat2(xv.y);
                ull a2_ = splat2(xv.z), a3 = splat2(xv.w);
                fma2(u2[j][0], a0,  w0l); fma2(u2[j][1], a0,  w0h);
                fma2(u2[j][0], a1,  w1l); fma2(u2[j][1], a1,  w1h);
                fma2(u2[j][0], a2_, w2l); fma2(u2[j][1], a2_, w2h);
                fma2(u2[j][0], a3,  w3l); fma2(u2[j][1], a3,  w3h);
            }
        }
        float u[5][4];
#pragma unroll
        for (int j = 0; j < 5; j++) {
            float2 lo = unpack2(u2[j][0]), hi = unpack2(u2[j][1]);
            u[j][0] = lo.x; u[j][1] = lo.y; u[j][2] = hi.x; u[j][3] = hi.y;
        }

        // ---- target path: ub[h] = Wt @ x_t (Wt from global/L1), reduce over nI
        float ub[4] = {0.f, 0.f, 0.f, 0.f};
#pragma unroll
        for (int t = 0; t < 2; t++) {
            int c4 = 2 * nI + t;
            float4 xv = xw4[35 * 16 + (c4 ^ 3)];   // 35&7 == 3
#pragma unroll
            for (int i = 0; i < 4; i++) {
                float4 w = __ldg(&WtP_g[c4 * 16 + i * 4 + hI]);
                float xs_ = (i == 0) ? xv.x : (i == 1) ? xv.y : (i == 2) ? xv.z : xv.w;
                ub[0] = fmaf(xs_, w.x, ub[0]); ub[1] = fmaf(xs_, w.y, ub[1]);
                ub[2] = fmaf(xs_, w.z, ub[2]); ub[3] = fmaf(xs_, w.w, ub[3]);
            }
        }
#pragma unroll
        for (int m = 1; m <= 4; m <<= 1) {
#pragma unroll
            for (int k = 0; k < 4; k++) ub[k] += __shfl_xor_sync(0xffffffffu, ub[k], m);
        }
        {
            float4 cbv = __ldg(&CB_g[hI]);
            ub[0] += cbv.x; ub[1] += cbv.y; ub[2] += cbv.z; ub[3] += cbv.w;
        }

        // ---- phase 3: e_n, leaky relu, softmax over n
        float e[5];
#pragma unroll
        for (int j = 0; j < 5; j++) {
            float pe = 0.f;
#pragma unroll
            for (int k = 0; k < 4; k++) {
                float hv = fmaxf(u[j][k] + ub[k], 0.f);
                pe = fmaf(a2r[k], hv, pe);
            }
            pe += __shfl_xor_sync(0xffffffffu, pe, 8);
            pe += __shfl_xor_sync(0xffffffffu, pe, 16);
            float ev = pe + a2bias;
            e[j] = ev > 0.f ? ev : 0.2f * ev;
        }
        if (nI >= 3) e[4] = -INFINITY;

        float mx = e[0];
#pragma unroll
        for (int j = 1; j < 5; j++) mx = fmaxf(mx, e[j]);
#pragma unroll
        for (int m = 1; m <= 4; m <<= 1) mx = fmaxf(mx, __shfl_xor_sync(0xffffffffu, mx, m));

        float ax[5]; float sum = 0.f;
#pragma unroll
        for (int j = 0; j < 5; j++) { ax[j] = __expf(e[j] - mx); sum += ax[j]; }
#pragma unroll
        for (int m = 1; m <= 4; m <<= 1) sum += __shfl_xor_sync(0xffffffffu, sum, m);
        float rinv = 1.0f / sum;

        if (hI == 0) {
#pragma unroll
            for (int j = 0; j < 5; j++) {
                int n = nI + 8 * j;
                if (n < 36) a_s[wid][n] = ax[j] * rinv;   // n==35 -> exp(-inf)=0 pad
            }
        }
        __syncwarp();

        // ---- phase 4: s[c] = sum_n a_n x_n[c]   (lane owns c = 2*lane, 2*lane+1)
        float slo = 0.f, shi = 0.f;
#pragma unroll 6
        for (int q = 0; q < 18; q++) {
            float2 av = *(const float2*)&a_s[wid][2 * q];
            int r0 = 2 * q, r1 = r0 + 1;
            float2 x0 = *(const float2*)&xw[r0 * 64 + (((lane >> 1) ^ (r0 & 7)) << 2) + ((lane & 1) << 1)];
            float2 x1 = *(const float2*)&xw[r1 * 64 + (((lane >> 1) ^ (r1 & 7)) << 2) + ((lane & 1) << 1)];
            slo = fmaf(av.x, x0.x, slo); shi = fmaf(av.x, x0.y, shi);
            slo = fmaf(av.y, x1.x, slo); shi = fmaf(av.y, x1.y, shi);
        }
        *(float2*)&s_s[wid][2 * lane] = make_float2(slo, shi);
        __syncthreads();

        // ---- phase 5: out = elu(align_w @ s + align_b), block-coop, ar in regs
        float acc[4];
#pragma unroll
        for (int bb = 0; bb < 4; bb++) {
            float a = 0.f;
            const float4* sp = (const float4*)&s_s[bb][half * 32];
#pragma unroll
            for (int i4 = 0; i4 < 8; i4++) {
                float4 sv = sp[i4];
                a = fmaf(ar[i4 * 4 + 0], sv.x, a);
                a = fmaf(ar[i4 * 4 + 1], sv.y, a);
                a = fmaf(ar[i4 * 4 + 2], sv.z, a);
                a = fmaf(ar[i4 * 4 + 3], sv.w, a);
            }
            acc[bb] = a;
        }
        if (half == 1) {
#pragma unroll
            for (int bb = 0; bb < 4; bb++) part[bb][d] = acc[bb];
        }
        __syncthreads();
        if (half == 0) {
#pragma unroll
            for (int bb = 0; bb < 4; bb++) {
                float o = acc[bb] + part[bb][d] + ab;
                o = (o > 0.f) ? o : expm1f(o);
                out[(size_t)(g * 4 + bb) * 64 + d] = o;
            }
        }
    }
}

extern "C" void kernel_launch(void* const* d_in, const int* in_sizes, int n_in,
                              void* d_out, int out_size) {
    const float* x_target = (const float*)d_in[0];
    const float* x_neigh  = (const float*)d_in[1];
    const float* align_w  = (const float*)d_in[2];
    const float* align_b  = (const float*)d_in[3];
    const float* attn1_w  = (const float*)d_in[4];
    const float* attn1_b  = (const float*)d_in[5];
    const float* attn2_w  = (const float*)d_in[6];
    const float* attn2_b  = (const float*)d_in[7];
    float* out = (float*)d_out;

    prep_kernel<<<9, 128>>>(align_w, align_b, attn1_w, attn1_b);
    gat_kernel<<<GRID, 128>>>(x_target, x_neigh, align_w, align_b,
                              attn2_w, attn2_b, out);
}